// round 14
// baseline (speedup 1.0000x reference)
#include <cuda_runtime.h>
#include <cuda_fp16.h>

// ===========================================================================
// EuclideanCodebook: ind = argmax_c ( x·e_c - 0.5||e_c||^2 ), q = embed[ind].
// R14: SINGLE fp16 GEMM at R12's proven occ-2 config (BM=64, 256 thr, 2 CTA/SM,
// no spills). Epilogue: top-3 values + top-2 indices (cheap, R12-proven).
// Tiers (T = 0.014*||x||, ~25 sigma of fp16 score-diff error):
//   gap12 >= T -> done ; gap13 >= T -> pair re-score {i0,i1} ; else warp-
//   collective full exact scan.
// ===========================================================================

#define NROWS   131072
#define KCODES  1024
#define BM      64
#define STRIDE_A 272            // A row: 256B payload (fp16 x) + 16B pad
#define STRIDE_B 272            // B row: 256B payload (fp16 e) + 16B pad

// smem byte offsets
#define S_HN    0                         // 1024 floats
#define S_XN    4096                      // 64 floats (row ||x||^2)
#define S_A     4352                      // 64 x 272 = 17408
#define S_B0    (S_A  + 17408)            // 21760 ; 128 x 272
#define S_B1    (S_B0 + 34816)            // 56576
#define S_V0    (S_B1 + 34816)            // 91392 ; float[4][64]
#define S_V1    (S_V0 + 1024)
#define S_V2    (S_V1 + 1024)
#define S_I0    (S_V2 + 1024)             // int[4][64]
#define S_I1    (S_I0 + 1024)
#define S_IND   (S_I1 + 1024)             // int[64]
#define S_TOTAL (S_IND + 256)             // 96768 B (2 CTA resident)

// __device__ scratch (allocation-free)
__device__ __align__(16) __half g_Eh[KCODES * 128];
__device__ float g_hn[KCODES];
__device__ int   g_pcnt;                  // pair-rescue count
__device__ int4  g_pjobs[NROWS];          // {row, i0, i1, 0}
__device__ int   g_fcnt;                  // full-rescue count
__device__ int   g_frows[NROWS];

// ---------------------------------------------------------------------------
__device__ __forceinline__ unsigned smem_u32(const void* p) {
    unsigned a;
    asm("{ .reg .u64 t; cvta.to.shared.u64 t, %1; cvt.u32.u64 %0, t; }"
        : "=r"(a) : "l"(p));
    return a;
}

#define LDSM_X4(r, addr)                                                      \
    asm volatile("ldmatrix.sync.aligned.m8n8.x4.shared.b16 {%0,%1,%2,%3}, [%4];" \
        : "=r"((r)[0]), "=r"((r)[1]), "=r"((r)[2]), "=r"((r)[3]) : "r"(addr))

#define MMA16816(d, a, b0, b1)                                                \
    asm volatile("mma.sync.aligned.m16n8k16.row.col.f32.f16.f16.f32 "        \
        "{%0,%1,%2,%3}, {%4,%5,%6,%7}, {%8,%9}, {%0,%1,%2,%3};"               \
        : "+f"((d)[0]), "+f"((d)[1]), "+f"((d)[2]), "+f"((d)[3])              \
        : "r"((a)[0]), "r"((a)[1]), "r"((a)[2]), "r"((a)[3]), "r"(b0), "r"(b1))

#define CP_COMMIT() asm volatile("cp.async.commit_group;" ::: "memory")
#define CP_WAIT1()  asm volatile("cp.async.wait_group 1;" ::: "memory")

// top-3 values, top-2 indices; ties -> lower index
struct Top3 { float V0, V1, V2; int I0, I1; };
__device__ __forceinline__ void t3_init(Top3& t) {
    t.V0 = t.V1 = t.V2 = -3.4e38f;
    t.I0 = t.I1 = 0x7fffffff;
}
__device__ __forceinline__ void t3_ins(Top3& t, float v, int i) {
    if (v > t.V0 || (v == t.V0 && i < t.I0)) {
        t.V2 = t.V1; t.V1 = t.V0; t.I1 = t.I0; t.V0 = v; t.I0 = i;
    } else if (v > t.V1 || (v == t.V1 && i < t.I1)) {
        t.V2 = t.V1; t.V1 = v; t.I1 = i;
    } else if (v > t.V2) {
        t.V2 = v;
    }
}

// ---------------------------------------------------------------------------
// prep_e: warp per code. fp16 convert + 0.5||e||^2 + counter reset.
// ---------------------------------------------------------------------------
__global__ void prep_e(const float* __restrict__ embed) {
    int w = (blockIdx.x * blockDim.x + threadIdx.x) >> 5;   // code
    int lane = threadIdx.x & 31;
    if (w == 0 && lane == 0) { g_pcnt = 0; g_fcnt = 0; }
    if (w >= KCODES) return;
    float4 v = ((const float4*)(embed + (size_t)w * 128))[lane];
    float s = v.x * v.x + v.y * v.y + v.z * v.z + v.w * v.w;
#pragma unroll
    for (int off = 16; off > 0; off >>= 1)
        s += __shfl_xor_sync(0xffffffffu, s, off);
    if (lane == 0) g_hn[w] = 0.5f * s;
    __half2 h0 = __floats2half2_rn(v.x, v.y);
    __half2 h1 = __floats2half2_rn(v.z, v.w);
    uint2 o; o.x = *(unsigned*)&h0; o.y = *(unsigned*)&h1;
    ((uint2*)(g_Eh + (size_t)w * 128))[lane] = o;
}

// ---------------------------------------------------------------------------
__device__ __forceinline__ void load_B_async(unsigned sb, int ch, int bufOff, int tid) {
    const char* src = (const char*)(g_Eh + (size_t)ch * 128 * 128);
#pragma unroll
    for (int it = 0; it < 8; it++) {
        int idx = tid + it * 256;
        int r = idx >> 4, kk = idx & 15;
        unsigned dst = sb + bufOff + r * STRIDE_B + kk * 16;
        asm volatile("cp.async.cg.shared.global [%0], [%1], 16;"
                     :: "r"(dst), "l"(src + r * 256 + kk * 16));
    }
}

// ---------------------------------------------------------------------------
// main: 2048 CTAs x 256 threads, 2 CTAs/SM; CTA = 64 rows x 1024 codes.
// Warps 2(row) x 4(code); warp tile 32 x 32. Single fp16 term.
// ---------------------------------------------------------------------------
__global__ __launch_bounds__(256, 2)
void vq_main(const float* __restrict__ x, const float* __restrict__ embed,
             float* __restrict__ out_ind, float* __restrict__ out_q) {
    extern __shared__ char smem[];
    unsigned sb = smem_u32(smem);
    const int tid  = threadIdx.x;
    const int lane = tid & 31, wid = tid >> 5;
    const int wr = wid & 1, wc = wid >> 1;
    const int rowBase = blockIdx.x * BM;
    float* hnS = (float*)(smem + S_HN);
    float* xnS = (float*)(smem + S_XN);

    // ---- prologue: hn + fused x->fp16 A tile (+ row norms) ----
    ((float4*)hnS)[tid] = ((const float4*)g_hn)[tid];
    {
        const float4* src = (const float4*)(x + (size_t)rowBase * 128);
#pragma unroll
        for (int it = 0; it < 8; it++) {
            int idx = tid + it * 256;
            int r = idx >> 5, kk = idx & 31;    // one warp covers one row
            float4 v = src[idx];
            float loc = v.x * v.x + v.y * v.y + v.z * v.z + v.w * v.w;
            __half2 h0 = __floats2half2_rn(v.x, v.y);
            __half2 h1 = __floats2half2_rn(v.z, v.w);
            uint2 hi; hi.x = *(unsigned*)&h0; hi.y = *(unsigned*)&h1;
            *(uint2*)(smem + S_A + r * STRIDE_A + kk * 8) = hi;
#pragma unroll
            for (int off = 16; off > 0; off >>= 1)
                loc += __shfl_xor_sync(0xffffffffu, loc, off);
            if (kk == 0) xnS[r] = loc;
        }
    }
    load_B_async(sb, 0, S_B0, tid); CP_COMMIT();
    load_B_async(sb, 1, S_B1, tid); CP_COMMIT();

    Top3 t3[4];
#pragma unroll
    for (int s = 0; s < 4; s++) t3_init(t3[s]);

    const unsigned aRowOff = (unsigned)(wr * 32 + (lane & 15)) * STRIDE_A
                             + ((lane >> 4) * 16);
    const unsigned bRowOff = (unsigned)(wc * 32 + ((lane >> 4) * 8) + (lane & 7)) * STRIDE_B
                             + (((lane >> 3) & 1) * 16);

    for (int ch = 0; ch < 8; ch++) {
        CP_WAIT1();
        __syncthreads();                       // chunk ch resident

        float d[2][4][4];
#pragma unroll
        for (int mt = 0; mt < 2; mt++)
#pragma unroll
            for (int nt = 0; nt < 4; nt++)
#pragma unroll
                for (int e = 0; e < 4; e++) d[mt][nt][e] = 0.f;

        const unsigned Abase = sb + S_A + aRowOff;
        const unsigned Bbase = sb + ((ch & 1) ? S_B1 : S_B0) + bRowOff;

#pragma unroll
        for (int kk = 0; kk < 8; kk++) {
            unsigned ah[2][4];
#pragma unroll
            for (int mt = 0; mt < 2; mt++)
                LDSM_X4(ah[mt], Abase + mt * (16 * STRIDE_A) + kk * 32);
            unsigned bh[2][4];
#pragma unroll
            for (int j = 0; j < 2; j++)
                LDSM_X4(bh[j], Bbase + j * (16 * STRIDE_B) + kk * 32);
#pragma unroll
            for (int mt = 0; mt < 2; mt++)
#pragma unroll
                for (int nt = 0; nt < 4; nt++)
                    MMA16816(d[mt][nt], ah[mt],
                             bh[nt >> 1][(nt & 1) * 2],
                             bh[nt >> 1][(nt & 1) * 2 + 1]);
        }

        // ---- fold -0.5||e||^2, update per-row-slot top-3 ----
        const int cb = ch * 128 + wc * 32 + (lane & 3) * 2;
#pragma unroll
        for (int mt = 0; mt < 2; mt++)
#pragma unroll
            for (int h = 0; h < 2; h++) {
                const int s = mt * 2 + h;
#pragma unroll
                for (int nt = 0; nt < 4; nt++)
#pragma unroll
                    for (int e = 0; e < 2; e++) {
                        int code = cb + nt * 8 + e;
                        float v = d[mt][nt][h * 2 + e] - hnS[code];
                        t3_ins(t3[s], v, code);
                    }
            }

        __syncthreads();
        if (ch + 2 < 8) { load_B_async(sb, ch + 2, (ch & 1) ? S_B1 : S_B0, tid); CP_COMMIT(); }
    }

    // ---- merge top-3 across 4 lanes sharing each row (xor 1, 2) ----
#pragma unroll
    for (int s = 0; s < 4; s++) {
#pragma unroll
        for (int off = 1; off <= 2; off <<= 1) {
            float oV0 = __shfl_xor_sync(0xffffffffu, t3[s].V0, off);
            float oV1 = __shfl_xor_sync(0xffffffffu, t3[s].V1, off);
            float oV2 = __shfl_xor_sync(0xffffffffu, t3[s].V2, off);
            int   oI0 = __shfl_xor_sync(0xffffffffu, t3[s].I0, off);
            int   oI1 = __shfl_xor_sync(0xffffffffu, t3[s].I1, off);
            t3_ins(t3[s], oV0, oI0);
            t3_ins(t3[s], oV1, oI1);
            t3_ins(t3[s], oV2, 0x7fffffff);
        }
    }
    if ((lane & 3) == 0) {
#pragma unroll
        for (int s = 0; s < 4; s++) {
            int mt = s >> 1, h = s & 1;
            int r = wr * 32 + mt * 16 + h * 8 + (lane >> 2);
            int o = wc * 64 + r;
            ((float*)(smem + S_V0))[o] = t3[s].V0;
            ((float*)(smem + S_V1))[o] = t3[s].V1;
            ((float*)(smem + S_V2))[o] = t3[s].V2;
            ((int*)(smem + S_I0))[o]   = t3[s].I0;
            ((int*)(smem + S_I1))[o]   = t3[s].I1;
        }
    }
    __syncthreads();

    // ---- merge 4 strips, write ind, classify rescue tiers ----
    if (tid < BM) {
        Top3 t; t3_init(t);
#pragma unroll
        for (int w = 0; w < 4; w++) {
            int o = w * 64 + tid;
            t3_ins(t, ((const float*)(smem + S_V0))[o], ((const int*)(smem + S_I0))[o]);
            t3_ins(t, ((const float*)(smem + S_V1))[o], ((const int*)(smem + S_I1))[o]);
            t3_ins(t, ((const float*)(smem + S_V2))[o], 0x7fffffff);
        }
        int row = rowBase + tid;
        if (out_ind) out_ind[row] = (float)t.I0;
        float T = 0.014f * sqrtf(xnS[tid]);
        if (t.V0 - t.V1 < T) {
            if (t.V0 - t.V2 >= T) {
                int s = atomicAdd(&g_pcnt, 1);
                if (s < NROWS) g_pjobs[s] = make_int4(row, t.I0, t.I1, 0);
            } else {
                int s = atomicAdd(&g_fcnt, 1);
                if (s < NROWS) g_frows[s] = row;
            }
        }
        ((int*)(smem + S_IND))[tid] = t.I0;
    }
    __syncthreads();

    // ---- cooperative gather of quantize rows ----
    if (out_q) {
        const int* inds = (const int*)(smem + S_IND);
        for (int i = tid; i < BM * 32; i += 256) {
            int r = i >> 5, c4 = i & 31;
            float4 v = ((const float4*)(embed + (size_t)inds[r] * 128))[c4];
            ((float4*)(out_q + (size_t)(rowBase + r) * 128))[c4] = v;
        }
    }
}

// ---------------------------------------------------------------------------
// pair rescue: warp per flagged row; exactly re-score 2 candidate codes.
// ---------------------------------------------------------------------------
__global__ __launch_bounds__(256, 8)
void pair_rescue(const float* __restrict__ x,
                 const float* __restrict__ embed,
                 float* __restrict__ out_ind,
                 float* __restrict__ out_q) {
    const int lane = threadIdx.x & 31;
    const int gw = (blockIdx.x * blockDim.x + threadIdx.x) >> 5;
    const int nw = (gridDim.x * blockDim.x) >> 5;
    const int cnt = g_pcnt < NROWS ? g_pcnt : NROWS;

    for (int it = gw; it < cnt; it += nw) {
        int4 job = g_pjobs[it];
        float4 xv = ((const float4*)(x + (size_t)job.x * 128))[lane];
        float s[2];
        int   idx[2] = {job.y, job.z};
#pragma unroll
        for (int c = 0; c < 2; c++) {
            float4 ev = ((const float4*)(embed + (size_t)idx[c] * 128))[lane];
            float p = fmaf(xv.x, ev.x, fmaf(xv.y, ev.y,
                      fmaf(xv.z, ev.z, xv.w * ev.w)));
#pragma unroll
            for (int off = 16; off > 0; off >>= 1)
                p += __shfl_xor_sync(0xffffffffu, p, off);
            s[c] = p - g_hn[idx[c]];
        }
        float B = s[0]; int I = idx[0];
        if (s[1] > B || (s[1] == B && idx[1] < I)) { B = s[1]; I = idx[1]; }
        if (lane == 0 && out_ind) out_ind[job.x] = (float)I;
        if (out_q)
            ((float4*)(out_q + (size_t)job.x * 128))[lane] =
                ((const float4*)(embed + (size_t)I * 128))[lane];
    }
}

// ---------------------------------------------------------------------------
// full rescue: warp per rare row; exact fp32 scan over all codes, lane-
// parallel over dims (codes visited in ascending order -> first-max ties).
// ---------------------------------------------------------------------------
__global__ __launch_bounds__(256, 8)
void full_rescue(const float* __restrict__ x,
                 const float* __restrict__ embed,
                 float* __restrict__ out_ind,
                 float* __restrict__ out_q) {
    const int lane = threadIdx.x & 31;
    const int gw = (blockIdx.x * blockDim.x + threadIdx.x) >> 5;
    const int nw = (gridDim.x * blockDim.x) >> 5;
    const int cnt = g_fcnt < NROWS ? g_fcnt : NROWS;

    for (int it = gw; it < cnt; it += nw) {
        int row = g_frows[it];
        float4 xv = ((const float4*)(x + (size_t)row * 128))[lane];
        float bv = -3.4e38f;
        int   bi = 0;
#pragma unroll 4
        for (int c = 0; c < KCODES; c++) {
            float4 ev = ((const float4*)(embed + (size_t)c * 128))[lane];
            float p = fmaf(xv.x, ev.x, fmaf(xv.y, ev.y,
                      fmaf(xv.z, ev.z, xv.w * ev.w)));
#pragma unroll
            for (int off = 16; off > 0; off >>= 1)
                p += __shfl_xor_sync(0xffffffffu, p, off);
            p -= g_hn[c];
            if (p > bv) { bv = p; bi = c; }
        }
        if (lane == 0 && out_ind) out_ind[row] = (float)bi;
        if (out_q)
            ((float4*)(out_q + (size_t)row * 128))[lane] =
                ((const float4*)(embed + (size_t)bi * 128))[lane];
    }
}

// ---------------------------------------------------------------------------
extern "C" void kernel_launch(void* const* d_in, const int* in_sizes, int n_in,
                              void* d_out, int out_size) {
    const float* x     = (const float*)d_in[0];
    const float* embed = (const float*)d_in[1];
    const int N = in_sizes[0] / 128;   // 131072

    float* out     = (float*)d_out;
    float* out_ind = out;              // layout: [ind (N)][quantize (N*128)]
    float* out_q   = out + N;
    long long os = (long long)out_size;
    if (os == (long long)N * 128) { out_ind = nullptr; out_q = out; }
    else if (os == (long long)N)  { out_q = nullptr; }

    prep_e<<<KCODES / 8, 256>>>(embed);

    cudaFuncSetAttribute(vq_main, cudaFuncAttributeMaxDynamicSharedMemorySize,
                         S_TOTAL);
    vq_main<<<N / BM, 256, S_TOTAL>>>(x, embed, out_ind, out_q);

    pair_rescue<<<512, 256>>>(x, embed, out_ind, out_q);
    full_rescue<<<512, 256>>>(x, embed, out_ind, out_q);
}

// round 15
// speedup vs baseline: 1.4132x; 1.4132x over previous
#include <cuda_runtime.h>
#include <cuda_fp16.h>

// ===========================================================================
// EuclideanCodebook: ind = argmax_c ( x·e_c - 0.5||e_c||^2 ), q = embed[ind].
// R15: SINGLE fp16 GEMM main (R14, ~100us at occ 2) + tiered rescue with the
// PARALLEL block-per-row full scan (R13-proven) instead of R14's serial
// warp-per-row scan (which was 430us).
// Tiers (T = 0.014*||x||): gap12 >= T done; gap13 >= T pair; else full.
// ===========================================================================

#define NROWS   131072
#define KCODES  1024
#define BM      64
#define STRIDE_A 272            // A row: 256B payload (fp16 x) + 16B pad
#define STRIDE_B 272            // B row: 256B payload (fp16 e) + 16B pad

// smem byte offsets
#define S_HN    0                         // 1024 floats
#define S_XN    4096                      // 64 floats (row ||x||^2)
#define S_A     4352                      // 64 x 272 = 17408
#define S_B0    (S_A  + 17408)            // 21760 ; 128 x 272
#define S_B1    (S_B0 + 34816)            // 56576
#define S_V0    (S_B1 + 34816)            // 91392 ; float[4][64]
#define S_V1    (S_V0 + 1024)
#define S_V2    (S_V1 + 1024)
#define S_I0    (S_V2 + 1024)             // int[4][64]
#define S_I1    (S_I0 + 1024)
#define S_IND   (S_I1 + 1024)             // int[64]
#define S_TOTAL (S_IND + 256)             // 96768 B (2 CTA resident)

// __device__ scratch (allocation-free)
__device__ __align__(16) __half g_Eh[KCODES * 128];
__device__ float g_hn[KCODES];
__device__ int   g_pcnt;                  // pair-rescue count
__device__ int4  g_pjobs[NROWS];          // {row, i0, i1, 0}
__device__ int   g_fcnt;                  // full-rescue count
__device__ int   g_frows[NROWS];

// ---------------------------------------------------------------------------
__device__ __forceinline__ unsigned smem_u32(const void* p) {
    unsigned a;
    asm("{ .reg .u64 t; cvta.to.shared.u64 t, %1; cvt.u32.u64 %0, t; }"
        : "=r"(a) : "l"(p));
    return a;
}

#define LDSM_X4(r, addr)                                                      \
    asm volatile("ldmatrix.sync.aligned.m8n8.x4.shared.b16 {%0,%1,%2,%3}, [%4];" \
        : "=r"((r)[0]), "=r"((r)[1]), "=r"((r)[2]), "=r"((r)[3]) : "r"(addr))

#define MMA16816(d, a, b0, b1)                                                \
    asm volatile("mma.sync.aligned.m16n8k16.row.col.f32.f16.f16.f32 "        \
        "{%0,%1,%2,%3}, {%4,%5,%6,%7}, {%8,%9}, {%0,%1,%2,%3};"               \
        : "+f"((d)[0]), "+f"((d)[1]), "+f"((d)[2]), "+f"((d)[3])              \
        : "r"((a)[0]), "r"((a)[1]), "r"((a)[2]), "r"((a)[3]), "r"(b0), "r"(b1))

#define CP_COMMIT() asm volatile("cp.async.commit_group;" ::: "memory")
#define CP_WAIT1()  asm volatile("cp.async.wait_group 1;" ::: "memory")

// top-3 values, top-2 indices; ties -> lower index
struct Top3 { float V0, V1, V2; int I0, I1; };
__device__ __forceinline__ void t3_init(Top3& t) {
    t.V0 = t.V1 = t.V2 = -3.4e38f;
    t.I0 = t.I1 = 0x7fffffff;
}
__device__ __forceinline__ void t3_ins(Top3& t, float v, int i) {
    if (v > t.V0 || (v == t.V0 && i < t.I0)) {
        t.V2 = t.V1; t.V1 = t.V0; t.I1 = t.I0; t.V0 = v; t.I0 = i;
    } else if (v > t.V1 || (v == t.V1 && i < t.I1)) {
        t.V2 = t.V1; t.V1 = v; t.I1 = i;
    } else if (v > t.V2) {
        t.V2 = v;
    }
}

// ---------------------------------------------------------------------------
// prep_e: warp per code. fp16 convert + 0.5||e||^2 + counter reset.
// ---------------------------------------------------------------------------
__global__ void prep_e(const float* __restrict__ embed) {
    int w = (blockIdx.x * blockDim.x + threadIdx.x) >> 5;   // code
    int lane = threadIdx.x & 31;
    if (w == 0 && lane == 0) { g_pcnt = 0; g_fcnt = 0; }
    if (w >= KCODES) return;
    float4 v = ((const float4*)(embed + (size_t)w * 128))[lane];
    float s = v.x * v.x + v.y * v.y + v.z * v.z + v.w * v.w;
#pragma unroll
    for (int off = 16; off > 0; off >>= 1)
        s += __shfl_xor_sync(0xffffffffu, s, off);
    if (lane == 0) g_hn[w] = 0.5f * s;
    __half2 h0 = __floats2half2_rn(v.x, v.y);
    __half2 h1 = __floats2half2_rn(v.z, v.w);
    uint2 o; o.x = *(unsigned*)&h0; o.y = *(unsigned*)&h1;
    ((uint2*)(g_Eh + (size_t)w * 128))[lane] = o;
}

// ---------------------------------------------------------------------------
__device__ __forceinline__ void load_B_async(unsigned sb, int ch, int bufOff, int tid) {
    const char* src = (const char*)(g_Eh + (size_t)ch * 128 * 128);
#pragma unroll
    for (int it = 0; it < 8; it++) {
        int idx = tid + it * 256;
        int r = idx >> 4, kk = idx & 15;
        unsigned dst = sb + bufOff + r * STRIDE_B + kk * 16;
        asm volatile("cp.async.cg.shared.global [%0], [%1], 16;"
                     :: "r"(dst), "l"(src + r * 256 + kk * 16));
    }
}

// ---------------------------------------------------------------------------
// main: 2048 CTAs x 256 threads, 2 CTAs/SM; CTA = 64 rows x 1024 codes.
// Warps 2(row) x 4(code); warp tile 32 x 32. Single fp16 term.
// ---------------------------------------------------------------------------
__global__ __launch_bounds__(256, 2)
void vq_main(const float* __restrict__ x, const float* __restrict__ embed,
             float* __restrict__ out_ind, float* __restrict__ out_q) {
    extern __shared__ char smem[];
    unsigned sb = smem_u32(smem);
    const int tid  = threadIdx.x;
    const int lane = tid & 31, wid = tid >> 5;
    const int wr = wid & 1, wc = wid >> 1;
    const int rowBase = blockIdx.x * BM;
    float* hnS = (float*)(smem + S_HN);
    float* xnS = (float*)(smem + S_XN);

    // ---- prologue: hn + fused x->fp16 A tile (+ row norms) ----
    ((float4*)hnS)[tid] = ((const float4*)g_hn)[tid];
    {
        const float4* src = (const float4*)(x + (size_t)rowBase * 128);
#pragma unroll
        for (int it = 0; it < 8; it++) {
            int idx = tid + it * 256;
            int r = idx >> 5, kk = idx & 31;    // one warp covers one row
            float4 v = src[idx];
            float loc = v.x * v.x + v.y * v.y + v.z * v.z + v.w * v.w;
            __half2 h0 = __floats2half2_rn(v.x, v.y);
            __half2 h1 = __floats2half2_rn(v.z, v.w);
            uint2 hi; hi.x = *(unsigned*)&h0; hi.y = *(unsigned*)&h1;
            *(uint2*)(smem + S_A + r * STRIDE_A + kk * 8) = hi;
#pragma unroll
            for (int off = 16; off > 0; off >>= 1)
                loc += __shfl_xor_sync(0xffffffffu, loc, off);
            if (kk == 0) xnS[r] = loc;
        }
    }
    load_B_async(sb, 0, S_B0, tid); CP_COMMIT();
    load_B_async(sb, 1, S_B1, tid); CP_COMMIT();

    Top3 t3[4];
#pragma unroll
    for (int s = 0; s < 4; s++) t3_init(t3[s]);

    const unsigned aRowOff = (unsigned)(wr * 32 + (lane & 15)) * STRIDE_A
                             + ((lane >> 4) * 16);
    const unsigned bRowOff = (unsigned)(wc * 32 + ((lane >> 4) * 8) + (lane & 7)) * STRIDE_B
                             + (((lane >> 3) & 1) * 16);

    for (int ch = 0; ch < 8; ch++) {
        CP_WAIT1();
        __syncthreads();                       // chunk ch resident

        float d[2][4][4];
#pragma unroll
        for (int mt = 0; mt < 2; mt++)
#pragma unroll
            for (int nt = 0; nt < 4; nt++)
#pragma unroll
                for (int e = 0; e < 4; e++) d[mt][nt][e] = 0.f;

        const unsigned Abase = sb + S_A + aRowOff;
        const unsigned Bbase = sb + ((ch & 1) ? S_B1 : S_B0) + bRowOff;

#pragma unroll
        for (int kk = 0; kk < 8; kk++) {
            unsigned ah[2][4];
#pragma unroll
            for (int mt = 0; mt < 2; mt++)
                LDSM_X4(ah[mt], Abase + mt * (16 * STRIDE_A) + kk * 32);
            unsigned bh[2][4];
#pragma unroll
            for (int j = 0; j < 2; j++)
                LDSM_X4(bh[j], Bbase + j * (16 * STRIDE_B) + kk * 32);
#pragma unroll
            for (int mt = 0; mt < 2; mt++)
#pragma unroll
                for (int nt = 0; nt < 4; nt++)
                    MMA16816(d[mt][nt], ah[mt],
                             bh[nt >> 1][(nt & 1) * 2],
                             bh[nt >> 1][(nt & 1) * 2 + 1]);
        }

        // ---- fold -0.5||e||^2, update per-row-slot top-3 ----
        const int cb = ch * 128 + wc * 32 + (lane & 3) * 2;
#pragma unroll
        for (int mt = 0; mt < 2; mt++)
#pragma unroll
            for (int h = 0; h < 2; h++) {
                const int s = mt * 2 + h;
#pragma unroll
                for (int nt = 0; nt < 4; nt++)
#pragma unroll
                    for (int e = 0; e < 2; e++) {
                        int code = cb + nt * 8 + e;
                        float v = d[mt][nt][h * 2 + e] - hnS[code];
                        t3_ins(t3[s], v, code);
                    }
            }

        __syncthreads();
        if (ch + 2 < 8) { load_B_async(sb, ch + 2, (ch & 1) ? S_B1 : S_B0, tid); CP_COMMIT(); }
    }

    // ---- merge top-3 across 4 lanes sharing each row (xor 1, 2) ----
#pragma unroll
    for (int s = 0; s < 4; s++) {
#pragma unroll
        for (int off = 1; off <= 2; off <<= 1) {
            float oV0 = __shfl_xor_sync(0xffffffffu, t3[s].V0, off);
            float oV1 = __shfl_xor_sync(0xffffffffu, t3[s].V1, off);
            float oV2 = __shfl_xor_sync(0xffffffffu, t3[s].V2, off);
            int   oI0 = __shfl_xor_sync(0xffffffffu, t3[s].I0, off);
            int   oI1 = __shfl_xor_sync(0xffffffffu, t3[s].I1, off);
            t3_ins(t3[s], oV0, oI0);
            t3_ins(t3[s], oV1, oI1);
            t3_ins(t3[s], oV2, 0x7fffffff);
        }
    }
    if ((lane & 3) == 0) {
#pragma unroll
        for (int s = 0; s < 4; s++) {
            int mt = s >> 1, h = s & 1;
            int r = wr * 32 + mt * 16 + h * 8 + (lane >> 2);
            int o = wc * 64 + r;
            ((float*)(smem + S_V0))[o] = t3[s].V0;
            ((float*)(smem + S_V1))[o] = t3[s].V1;
            ((float*)(smem + S_V2))[o] = t3[s].V2;
            ((int*)(smem + S_I0))[o]   = t3[s].I0;
            ((int*)(smem + S_I1))[o]   = t3[s].I1;
        }
    }
    __syncthreads();

    // ---- merge 4 strips, write ind, classify rescue tiers ----
    if (tid < BM) {
        Top3 t; t3_init(t);
#pragma unroll
        for (int w = 0; w < 4; w++) {
            int o = w * 64 + tid;
            t3_ins(t, ((const float*)(smem + S_V0))[o], ((const int*)(smem + S_I0))[o]);
            t3_ins(t, ((const float*)(smem + S_V1))[o], ((const int*)(smem + S_I1))[o]);
            t3_ins(t, ((const float*)(smem + S_V2))[o], 0x7fffffff);
        }
        int row = rowBase + tid;
        if (out_ind) out_ind[row] = (float)t.I0;
        float T = 0.014f * sqrtf(xnS[tid]);
        if (t.V0 - t.V1 < T) {
            if (t.V0 - t.V2 >= T) {
                int s = atomicAdd(&g_pcnt, 1);
                if (s < NROWS) g_pjobs[s] = make_int4(row, t.I0, t.I1, 0);
            } else {
                int s = atomicAdd(&g_fcnt, 1);
                if (s < NROWS) g_frows[s] = row;
            }
        }
        ((int*)(smem + S_IND))[tid] = t.I0;
    }
    __syncthreads();

    // ---- cooperative gather of quantize rows ----
    if (out_q) {
        const int* inds = (const int*)(smem + S_IND);
        for (int i = tid; i < BM * 32; i += 256) {
            int r = i >> 5, c4 = i & 31;
            float4 v = ((const float4*)(embed + (size_t)inds[r] * 128))[c4];
            ((float4*)(out_q + (size_t)(rowBase + r) * 128))[c4] = v;
        }
    }
}

// ---------------------------------------------------------------------------
// pair rescue: warp per flagged row; exactly re-score 2 candidate codes.
// ---------------------------------------------------------------------------
__global__ __launch_bounds__(256, 8)
void pair_rescue(const float* __restrict__ x,
                 const float* __restrict__ embed,
                 float* __restrict__ out_ind,
                 float* __restrict__ out_q) {
    const int lane = threadIdx.x & 31;
    const int gw = (blockIdx.x * blockDim.x + threadIdx.x) >> 5;
    const int nw = (gridDim.x * blockDim.x) >> 5;
    const int cnt = g_pcnt < NROWS ? g_pcnt : NROWS;

    for (int it = gw; it < cnt; it += nw) {
        int4 job = g_pjobs[it];
        float4 xv = ((const float4*)(x + (size_t)job.x * 128))[lane];
        float s[2];
        int   idx[2] = {job.y, job.z};
#pragma unroll
        for (int c = 0; c < 2; c++) {
            float4 ev = ((const float4*)(embed + (size_t)idx[c] * 128))[lane];
            float p = fmaf(xv.x, ev.x, fmaf(xv.y, ev.y,
                      fmaf(xv.z, ev.z, xv.w * ev.w)));
#pragma unroll
            for (int off = 16; off > 0; off >>= 1)
                p += __shfl_xor_sync(0xffffffffu, p, off);
            s[c] = p - g_hn[idx[c]];
        }
        float B = s[0]; int I = idx[0];
        if (s[1] > B || (s[1] == B && idx[1] < I)) { B = s[1]; I = idx[1]; }
        if (lane == 0 && out_ind) out_ind[job.x] = (float)I;
        if (out_q)
            ((float4*)(out_q + (size_t)job.x * 128))[lane] =
                ((const float4*)(embed + (size_t)I * 128))[lane];
    }
}

// ---------------------------------------------------------------------------
// full rescue: BLOCK per row (parallel over codes: 256 thr x 4 codes each).
// ---------------------------------------------------------------------------
__global__ __launch_bounds__(256, 4)
void full_rescue(const float* __restrict__ x,
                 const float* __restrict__ embed,
                 float* __restrict__ out_ind,
                 float* __restrict__ out_q) {
    __shared__ float4 xs4[32];
    __shared__ float bvs[256];
    __shared__ int   bis[256];
    const int tid = threadIdx.x;
    const int cnt = g_fcnt < NROWS ? g_fcnt : NROWS;

    for (int it = blockIdx.x; it < cnt; it += gridDim.x) {
        int row = g_frows[it];
        if (tid < 32) xs4[tid] = ((const float4*)(x + (size_t)row * 128))[tid];
        __syncthreads();

        float bv = -3.4e38f;
        int   bi = 0;
#pragma unroll
        for (int j = 0; j < 4; j++) {
            int c = j * 256 + tid;
            const float4* e4 = (const float4*)(embed + (size_t)c * 128);
            float s0 = 0.f, s1 = 0.f, s2 = 0.f, s3 = 0.f;
#pragma unroll
            for (int i = 0; i < 8; i++) {
                float4 xa = xs4[i * 4 + 0], ea = e4[i * 4 + 0];
                float4 xb = xs4[i * 4 + 1], eb = e4[i * 4 + 1];
                float4 xc = xs4[i * 4 + 2], ec = e4[i * 4 + 2];
                float4 xd = xs4[i * 4 + 3], ed = e4[i * 4 + 3];
                s0 = fmaf(xa.x, ea.x, fmaf(xa.y, ea.y, fmaf(xa.z, ea.z, fmaf(xa.w, ea.w, s0))));
                s1 = fmaf(xb.x, eb.x, fmaf(xb.y, eb.y, fmaf(xb.z, eb.z, fmaf(xb.w, eb.w, s1))));
                s2 = fmaf(xc.x, ec.x, fmaf(xc.y, ec.y, fmaf(xc.z, ec.z, fmaf(xc.w, ec.w, s2))));
                s3 = fmaf(xd.x, ed.x, fmaf(xd.y, ed.y, fmaf(xd.z, ed.z, fmaf(xd.w, ed.w, s3))));
            }
            float s = (s0 + s1) + (s2 + s3) - g_hn[c];
            if (s > bv) { bv = s; bi = c; }
        }
        bvs[tid] = bv; bis[tid] = bi;
        __syncthreads();
#pragma unroll
        for (int st = 128; st > 0; st >>= 1) {
            if (tid < st) {
                float ov = bvs[tid + st]; int oi = bis[tid + st];
                if (ov > bvs[tid] || (ov == bvs[tid] && oi < bis[tid])) {
                    bvs[tid] = ov; bis[tid] = oi;
                }
            }
            __syncthreads();
        }
        int fi = bis[0];
        if (tid == 0 && out_ind) out_ind[row] = (float)fi;
        if (out_q && tid < 32)
            ((float4*)(out_q + (size_t)row * 128))[tid] =
                ((const float4*)(embed + (size_t)fi * 128))[tid];
        __syncthreads();
    }
}

// ---------------------------------------------------------------------------
extern "C" void kernel_launch(void* const* d_in, const int* in_sizes, int n_in,
                              void* d_out, int out_size) {
    const float* x     = (const float*)d_in[0];
    const float* embed = (const float*)d_in[1];
    const int N = in_sizes[0] / 128;   // 131072

    float* out     = (float*)d_out;
    float* out_ind = out;              // layout: [ind (N)][quantize (N*128)]
    float* out_q   = out + N;
    long long os = (long long)out_size;
    if (os == (long long)N * 128) { out_ind = nullptr; out_q = out; }
    else if (os == (long long)N)  { out_q = nullptr; }

    prep_e<<<KCODES / 8, 256>>>(embed);

    cudaFuncSetAttribute(vq_main, cudaFuncAttributeMaxDynamicSharedMemorySize,
                         S_TOTAL);
    vq_main<<<N / BM, 256, S_TOTAL>>>(x, embed, out_ind, out_q);

    pair_rescue<<<512, 256>>>(x, embed, out_ind, out_q);
    full_rescue<<<2048, 256>>>(x, embed, out_ind, out_q);
}

// round 17
// speedup vs baseline: 1.5904x; 1.1254x over previous
#include <cuda_runtime.h>
#include <cuda_fp16.h>

// ===========================================================================
// EuclideanCodebook: ind = argmax_c ( x·e_c - 0.5||e_c||^2 ), q = embed[ind].
// R17: R16 (BN=64 chunks, 60.5KB smem, 3 CTAs/SM) with the B-fragment
// ldmatrix quadrant ordering FIXED (R15's proven lane mapping: code-octet
// major, k-half minor). Tiered rescue unchanged (T = 0.014*||x||).
// ===========================================================================

#define NROWS   131072
#define KCODES  1024
#define BM      64
#define BN      64
#define NCHUNK  (KCODES / BN)   // 16
#define STRIDE_A 272            // A row: 256B payload (fp16 x) + 16B pad
#define STRIDE_B 272            // B row: 256B payload (fp16 e) + 16B pad

// smem byte offsets
#define S_HN    0                         // 1024 floats
#define S_XN    4096                      // 64 floats (row ||x||^2)
#define S_A     4352                      // 64 x 272 = 17408
#define S_B0    (S_A  + 17408)            // 21760 ; 64 x 272 = 17408
#define S_B1    (S_B0 + 17408)            // 39168
#define S_V0    (S_B1 + 17408)            // 56576 ; float[4][64]
#define S_V1    (S_V0 + 1024)
#define S_V2    (S_V1 + 1024)
#define S_I0    (S_V2 + 1024)             // int[4][64]
#define S_I1    (S_I0 + 1024)
#define S_IND   (S_I1 + 1024)             // int[64]
#define S_TOTAL (S_IND + 256)             // 61952 B (3 CTAs resident)

// __device__ scratch (allocation-free)
__device__ __align__(16) __half g_Eh[KCODES * 128];
__device__ float g_hn[KCODES];
__device__ int   g_pcnt;                  // pair-rescue count
__device__ int4  g_pjobs[NROWS];          // {row, i0, i1, 0}
__device__ int   g_fcnt;                  // full-rescue count
__device__ int   g_frows[NROWS];

// ---------------------------------------------------------------------------
__device__ __forceinline__ unsigned smem_u32(const void* p) {
    unsigned a;
    asm("{ .reg .u64 t; cvta.to.shared.u64 t, %1; cvt.u32.u64 %0, t; }"
        : "=r"(a) : "l"(p));
    return a;
}

#define LDSM_X4(r, addr)                                                      \
    asm volatile("ldmatrix.sync.aligned.m8n8.x4.shared.b16 {%0,%1,%2,%3}, [%4];" \
        : "=r"((r)[0]), "=r"((r)[1]), "=r"((r)[2]), "=r"((r)[3]) : "r"(addr))

#define MMA16816(d, a, b0, b1)                                                \
    asm volatile("mma.sync.aligned.m16n8k16.row.col.f32.f16.f16.f32 "        \
        "{%0,%1,%2,%3}, {%4,%5,%6,%7}, {%8,%9}, {%0,%1,%2,%3};"               \
        : "+f"((d)[0]), "+f"((d)[1]), "+f"((d)[2]), "+f"((d)[3])              \
        : "r"((a)[0]), "r"((a)[1]), "r"((a)[2]), "r"((a)[3]), "r"(b0), "r"(b1))

#define CP_COMMIT() asm volatile("cp.async.commit_group;" ::: "memory")
#define CP_WAIT1()  asm volatile("cp.async.wait_group 1;" ::: "memory")

// top-3 values, top-2 indices; ties -> lower index
struct Top3 { float V0, V1, V2; int I0, I1; };
__device__ __forceinline__ void t3_init(Top3& t) {
    t.V0 = t.V1 = t.V2 = -3.4e38f;
    t.I0 = t.I1 = 0x7fffffff;
}
__device__ __forceinline__ void t3_ins(Top3& t, float v, int i) {
    if (v > t.V0 || (v == t.V0 && i < t.I0)) {
        t.V2 = t.V1; t.V1 = t.V0; t.I1 = t.I0; t.V0 = v; t.I0 = i;
    } else if (v > t.V1 || (v == t.V1 && i < t.I1)) {
        t.V2 = t.V1; t.V1 = v; t.I1 = i;
    } else if (v > t.V2) {
        t.V2 = v;
    }
}

// ---------------------------------------------------------------------------
// prep_e: warp per code. fp16 convert + 0.5||e||^2 + counter reset.
// ---------------------------------------------------------------------------
__global__ void prep_e(const float* __restrict__ embed) {
    int w = (blockIdx.x * blockDim.x + threadIdx.x) >> 5;   // code
    int lane = threadIdx.x & 31;
    if (w == 0 && lane == 0) { g_pcnt = 0; g_fcnt = 0; }
    if (w >= KCODES) return;
    float4 v = ((const float4*)(embed + (size_t)w * 128))[lane];
    float s = v.x * v.x + v.y * v.y + v.z * v.z + v.w * v.w;
#pragma unroll
    for (int off = 16; off > 0; off >>= 1)
        s += __shfl_xor_sync(0xffffffffu, s, off);
    if (lane == 0) g_hn[w] = 0.5f * s;
    __half2 h0 = __floats2half2_rn(v.x, v.y);
    __half2 h1 = __floats2half2_rn(v.z, v.w);
    uint2 o; o.x = *(unsigned*)&h0; o.y = *(unsigned*)&h1;
    ((uint2*)(g_Eh + (size_t)w * 128))[lane] = o;
}

// ---------------------------------------------------------------------------
// B chunk loader: 64 codes x 128 fp16 (256B/code). 4 cp.async per thread.
// ---------------------------------------------------------------------------
__device__ __forceinline__ void load_B_async(unsigned sb, int ch, int bufOff, int tid) {
    const char* src = (const char*)(g_Eh + (size_t)ch * BN * 128);
#pragma unroll
    for (int it = 0; it < 4; it++) {
        int idx = tid + it * 256;
        int r = idx >> 4, kk = idx & 15;
        unsigned dst = sb + bufOff + r * STRIDE_B + kk * 16;
        asm volatile("cp.async.cg.shared.global [%0], [%1], 16;"
                     :: "r"(dst), "l"(src + r * 256 + kk * 16));
    }
}

// ---------------------------------------------------------------------------
// main: 2048 CTAs x 256 threads, 3 CTAs/SM; CTA = 64 rows x 1024 codes
// (16 chunks of 64). Warps 2(row) x 4(code); warp tile 32 rows x 16 codes.
// ---------------------------------------------------------------------------
__global__ __launch_bounds__(256, 3)
void vq_main(const float* __restrict__ x, const float* __restrict__ embed,
             float* __restrict__ out_ind, float* __restrict__ out_q) {
    extern __shared__ char smem[];
    unsigned sb = smem_u32(smem);
    const int tid  = threadIdx.x;
    const int lane = tid & 31, wid = tid >> 5;
    const int wr = wid & 1, wc = wid >> 1;
    const int rowBase = blockIdx.x * BM;
    float* hnS = (float*)(smem + S_HN);
    float* xnS = (float*)(smem + S_XN);

    // ---- prologue: hn + fused x->fp16 A tile (+ row norms) ----
    ((float4*)hnS)[tid] = ((const float4*)g_hn)[tid];
    {
        const float4* src = (const float4*)(x + (size_t)rowBase * 128);
#pragma unroll
        for (int it = 0; it < 8; it++) {
            int idx = tid + it * 256;
            int r = idx >> 5, kk = idx & 31;    // one warp covers one row
            float4 v = src[idx];
            float loc = v.x * v.x + v.y * v.y + v.z * v.z + v.w * v.w;
            __half2 h0 = __floats2half2_rn(v.x, v.y);
            __half2 h1 = __floats2half2_rn(v.z, v.w);
            uint2 hi; hi.x = *(unsigned*)&h0; hi.y = *(unsigned*)&h1;
            *(uint2*)(smem + S_A + r * STRIDE_A + kk * 8) = hi;
#pragma unroll
            for (int off = 16; off > 0; off >>= 1)
                loc += __shfl_xor_sync(0xffffffffu, loc, off);
            if (kk == 0) xnS[r] = loc;
        }
    }
    load_B_async(sb, 0, S_B0, tid); CP_COMMIT();
    load_B_async(sb, 1, S_B1, tid); CP_COMMIT();

    Top3 t3[4];
#pragma unroll
    for (int s = 0; s < 4; s++) t3_init(t3[s]);

    const unsigned aRowOff = (unsigned)(wr * 32 + (lane & 15)) * STRIDE_A
                             + ((lane >> 4) * 16);
    // B: warp owns 16 codes. R15-proven quadrant order: code-octet major,
    // k-half minor -> matrices {c0-8/k0-8, c0-8/k8-16, c8-16/k0-8, c8-16/k8-16}
    const unsigned bRowOff = (unsigned)(wc * 16 + ((lane >> 4) * 8) + (lane & 7)) * STRIDE_B
                             + (((lane >> 3) & 1) * 16);

    for (int ch = 0; ch < NCHUNK; ch++) {
        CP_WAIT1();
        __syncthreads();                       // chunk ch resident

        float d[2][2][4];
#pragma unroll
        for (int mt = 0; mt < 2; mt++)
#pragma unroll
            for (int nt = 0; nt < 2; nt++)
#pragma unroll
                for (int e = 0; e < 4; e++) d[mt][nt][e] = 0.f;

        const unsigned Abase = sb + S_A + aRowOff;
        const unsigned Bbase = sb + ((ch & 1) ? S_B1 : S_B0) + bRowOff;

#pragma unroll
        for (int kk = 0; kk < 8; kk++) {
            unsigned ah[2][4];
#pragma unroll
            for (int mt = 0; mt < 2; mt++)
                LDSM_X4(ah[mt], Abase + mt * (16 * STRIDE_A) + kk * 32);
            unsigned bh[4];
            LDSM_X4(bh, Bbase + kk * 32);
#pragma unroll
            for (int mt = 0; mt < 2; mt++)
#pragma unroll
                for (int nt = 0; nt < 2; nt++)
                    MMA16816(d[mt][nt], ah[mt], bh[nt * 2], bh[nt * 2 + 1]);
        }

        // ---- fold -0.5||e||^2, update per-row-slot top-3 ----
        const int cb = ch * BN + wc * 16 + (lane & 3) * 2;
#pragma unroll
        for (int mt = 0; mt < 2; mt++)
#pragma unroll
            for (int h = 0; h < 2; h++) {
                const int s = mt * 2 + h;
#pragma unroll
                for (int nt = 0; nt < 2; nt++)
#pragma unroll
                    for (int e = 0; e < 2; e++) {
                        int code = cb + nt * 8 + e;
                        float v = d[mt][nt][h * 2 + e] - hnS[code];
                        t3_ins(t3[s], v, code);
                    }
            }

        __syncthreads();
        if (ch + 2 < NCHUNK) {
            load_B_async(sb, ch + 2, (ch & 1) ? S_B1 : S_B0, tid);
            CP_COMMIT();
        }
    }

    // ---- merge top-3 across 4 lanes sharing each row (xor 1, 2) ----
#pragma unroll
    for (int s = 0; s < 4; s++) {
#pragma unroll
        for (int off = 1; off <= 2; off <<= 1) {
            float oV0 = __shfl_xor_sync(0xffffffffu, t3[s].V0, off);
            float oV1 = __shfl_xor_sync(0xffffffffu, t3[s].V1, off);
            float oV2 = __shfl_xor_sync(0xffffffffu, t3[s].V2, off);
            int   oI0 = __shfl_xor_sync(0xffffffffu, t3[s].I0, off);
            int   oI1 = __shfl_xor_sync(0xffffffffu, t3[s].I1, off);
            t3_ins(t3[s], oV0, oI0);
            t3_ins(t3[s], oV1, oI1);
            t3_ins(t3[s], oV2, 0x7fffffff);
        }
    }
    if ((lane & 3) == 0) {
#pragma unroll
        for (int s = 0; s < 4; s++) {
            int mt = s >> 1, h = s & 1;
            int r = wr * 32 + mt * 16 + h * 8 + (lane >> 2);
            int o = wc * 64 + r;
            ((float*)(smem + S_V0))[o] = t3[s].V0;
            ((float*)(smem + S_V1))[o] = t3[s].V1;
            ((float*)(smem + S_V2))[o] = t3[s].V2;
            ((int*)(smem + S_I0))[o]   = t3[s].I0;
            ((int*)(smem + S_I1))[o]   = t3[s].I1;
        }
    }
    __syncthreads();

    // ---- merge 4 strips, write ind, classify rescue tiers ----
    if (tid < BM) {
        Top3 t; t3_init(t);
#pragma unroll
        for (int w = 0; w < 4; w++) {
            int o = w * 64 + tid;
            t3_ins(t, ((const float*)(smem + S_V0))[o], ((const int*)(smem + S_I0))[o]);
            t3_ins(t, ((const float*)(smem + S_V1))[o], ((const int*)(smem + S_I1))[o]);
            t3_ins(t, ((const float*)(smem + S_V2))[o], 0x7fffffff);
        }
        int row = rowBase + tid;
        if (out_ind) out_ind[row] = (float)t.I0;
        float T = 0.014f * sqrtf(xnS[tid]);
        if (t.V0 - t.V1 < T) {
            if (t.V0 - t.V2 >= T) {
                int s = atomicAdd(&g_pcnt, 1);
                if (s < NROWS) g_pjobs[s] = make_int4(row, t.I0, t.I1, 0);
            } else {
                int s = atomicAdd(&g_fcnt, 1);
                if (s < NROWS) g_frows[s] = row;
            }
        }
        ((int*)(smem + S_IND))[tid] = t.I0;
    }
    __syncthreads();

    // ---- cooperative gather of quantize rows ----
    if (out_q) {
        const int* inds = (const int*)(smem + S_IND);
        for (int i = tid; i < BM * 32; i += 256) {
            int r = i >> 5, c4 = i & 31;
            float4 v = ((const float4*)(embed + (size_t)inds[r] * 128))[c4];
            ((float4*)(out_q + (size_t)(rowBase + r) * 128))[c4] = v;
        }
    }
}

// ---------------------------------------------------------------------------
// pair rescue: warp per flagged row; exactly re-score 2 candidate codes.
// ---------------------------------------------------------------------------
__global__ __launch_bounds__(256, 8)
void pair_rescue(const float* __restrict__ x,
                 const float* __restrict__ embed,
                 float* __restrict__ out_ind,
                 float* __restrict__ out_q) {
    const int lane = threadIdx.x & 31;
    const int gw = (blockIdx.x * blockDim.x + threadIdx.x) >> 5;
    const int nw = (gridDim.x * blockDim.x) >> 5;
    const int cnt = g_pcnt < NROWS ? g_pcnt : NROWS;

    for (int it = gw; it < cnt; it += nw) {
        int4 job = g_pjobs[it];
        float4 xv = ((const float4*)(x + (size_t)job.x * 128))[lane];
        float s[2];
        int   idx[2] = {job.y, job.z};
#pragma unroll
        for (int c = 0; c < 2; c++) {
            float4 ev = ((const float4*)(embed + (size_t)idx[c] * 128))[lane];
            float p = fmaf(xv.x, ev.x, fmaf(xv.y, ev.y,
                      fmaf(xv.z, ev.z, xv.w * ev.w)));
#pragma unroll
            for (int off = 16; off > 0; off >>= 1)
                p += __shfl_xor_sync(0xffffffffu, p, off);
            s[c] = p - g_hn[idx[c]];
        }
        float B = s[0]; int I = idx[0];
        if (s[1] > B || (s[1] == B && idx[1] < I)) { B = s[1]; I = idx[1]; }
        if (lane == 0 && out_ind) out_ind[job.x] = (float)I;
        if (out_q)
            ((float4*)(out_q + (size_t)job.x * 128))[lane] =
                ((const float4*)(embed + (size_t)I * 128))[lane];
    }
}

// ---------------------------------------------------------------------------
// full rescue: BLOCK per row (parallel over codes: 256 thr x 4 codes each).
// ---------------------------------------------------------------------------
__global__ __launch_bounds__(256, 4)
void full_rescue(const float* __restrict__ x,
                 const float* __restrict__ embed,
                 float* __restrict__ out_ind,
                 float* __restrict__ out_q) {
    __shared__ float4 xs4[32];
    __shared__ float bvs[256];
    __shared__ int   bis[256];
    const int tid = threadIdx.x;
    const int cnt = g_fcnt < NROWS ? g_fcnt : NROWS;

    for (int it = blockIdx.x; it < cnt; it += gridDim.x) {
        int row = g_frows[it];
        if (tid < 32) xs4[tid] = ((const float4*)(x + (size_t)row * 128))[tid];
        __syncthreads();

        float bv = -3.4e38f;
        int   bi = 0;
#pragma unroll
        for (int j = 0; j < 4; j++) {
            int c = j * 256 + tid;
            const float4* e4 = (const float4*)(embed + (size_t)c * 128);
            float s0 = 0.f, s1 = 0.f, s2 = 0.f, s3 = 0.f;
#pragma unroll
            for (int i = 0; i < 8; i++) {
                float4 xa = xs4[i * 4 + 0], ea = e4[i * 4 + 0];
                float4 xb = xs4[i * 4 + 1], eb = e4[i * 4 + 1];
                float4 xc = xs4[i * 4 + 2], ec = e4[i * 4 + 2];
                float4 xd = xs4[i * 4 + 3], ed = e4[i * 4 + 3];
                s0 = fmaf(xa.x, ea.x, fmaf(xa.y, ea.y, fmaf(xa.z, ea.z, fmaf(xa.w, ea.w, s0))));
                s1 = fmaf(xb.x, eb.x, fmaf(xb.y, eb.y, fmaf(xb.z, eb.z, fmaf(xb.w, eb.w, s1))));
                s2 = fmaf(xc.x, ec.x, fmaf(xc.y, ec.y, fmaf(xc.z, ec.z, fmaf(xc.w, ec.w, s2))));
                s3 = fmaf(xd.x, ed.x, fmaf(xd.y, ed.y, fmaf(xd.z, ed.z, fmaf(xd.w, ed.w, s3))));
            }
            float s = (s0 + s1) + (s2 + s3) - g_hn[c];
            if (s > bv) { bv = s; bi = c; }
        }
        bvs[tid] = bv; bis[tid] = bi;
        __syncthreads();
#pragma unroll
        for (int st = 128; st > 0; st >>= 1) {
            if (tid < st) {
                float ov = bvs[tid + st]; int oi = bis[tid + st];
                if (ov > bvs[tid] || (ov == bvs[tid] && oi < bis[tid])) {
                    bvs[tid] = ov; bis[tid] = oi;
                }
            }
            __syncthreads();
        }
        int fi = bis[0];
        if (tid == 0 && out_ind) out_ind[row] = (float)fi;
        if (out_q && tid < 32)
            ((float4*)(out_q + (size_t)row * 128))[tid] =
                ((const float4*)(embed + (size_t)fi * 128))[tid];
        __syncthreads();
    }
}

// ---------------------------------------------------------------------------
extern "C" void kernel_launch(void* const* d_in, const int* in_sizes, int n_in,
                              void* d_out, int out_size) {
    const float* x     = (const float*)d_in[0];
    const float* embed = (const float*)d_in[1];
    const int N = in_sizes[0] / 128;   // 131072

    float* out     = (float*)d_out;
    float* out_ind = out;              // layout: [ind (N)][quantize (N*128)]
    float* out_q   = out + N;
    long long os = (long long)out_size;
    if (os == (long long)N * 128) { out_ind = nullptr; out_q = out; }
    else if (os == (long long)N)  { out_q = nullptr; }

    prep_e<<<KCODES / 8, 256>>>(embed);

    cudaFuncSetAttribute(vq_main, cudaFuncAttributeMaxDynamicSharedMemorySize,
                         S_TOTAL);
    vq_main<<<N / BM, 256, S_TOTAL>>>(x, embed, out_ind, out_q);

    pair_rescue<<<512, 256>>>(x, embed, out_ind, out_q);
    full_rescue<<<2048, 256>>>(x, embed, out_ind, out_q);
}